// round 14
// baseline (speedup 1.0000x reference)
#include <cuda_runtime.h>

#define BATCH 2048
#define ISIZE 2048
#define OSIZE 2048
#define NIN   6
#define KTAB  64

typedef unsigned long long ull;

// Static scratch: transposed x, xT[m][b]  (16 MB)
__device__ float g_xT[(size_t)ISIZE * BATCH];

__device__ __forceinline__ ull pack2(float lo, float hi) {
    ull r;
    asm("mov.b64 %0, {%1, %2};" : "=l"(r) : "f"(lo), "f"(hi));
    return r;
}
__device__ __forceinline__ ull dup2(float f) { return pack2(f, f); }
__device__ __forceinline__ ull fma2(ull a, ull b, ull c) {
    ull r;
    asm("fma.rn.f32x2 %0, %1, %2, %3;" : "=l"(r) : "l"(a), "l"(b), "l"(c));
    return r;
}
__device__ __forceinline__ float2 unpack2(ull v) {
    float2 f;
    asm("mov.b64 {%0, %1}, %2;" : "=f"(f.x), "=f"(f.y) : "l"(v));
    return f;
}

// ---------------------------------------------------------------------------
// Kernel 1: transpose x [BATCH][ISIZE] -> g_xT [ISIZE][BATCH]
// ---------------------------------------------------------------------------
__global__ void transpose_kernel(const float* __restrict__ x) {
    __shared__ float tile[32][33];
    int bx = blockIdx.x * 32;
    int by = blockIdx.y * 32;
    int tx = threadIdx.x, ty = threadIdx.y;
#pragma unroll
    for (int j = 0; j < 32; j += 8)
        tile[ty + j][tx] = x[(size_t)(by + ty + j) * ISIZE + bx + tx];
    __syncthreads();
#pragma unroll
    for (int j = 0; j < 32; j += 8)
        g_xT[(size_t)(bx + ty + j) * BATCH + by + tx] = tile[tx][ty + j];
}

// ---------------------------------------------------------------------------
// Kernel 2: LUT evaluation via Mobius-Horner (R9 core), tuned for OCCUPANCY:
//   __launch_bounds__(128, 8) pins 8 CTAs/SM (<=64 regs, 50% occ cap vs 43.75%).
//   Late dims loaded just-in-time (dim4 after group 1, dim5 after group 3)
//   to shorten live ranges so the kernel fits the 64-reg budget w/o spills.
//   Thread tile: 4 outputs x 4 contiguous batches (2 f32x2 pairs).
//   Grid 512 x 4 = 2048 CTAs.
// ---------------------------------------------------------------------------
#define OT      4
#define THREADS 128
#define BPT     4
#define BT      (THREADS * BPT)   // 512

__global__ __launch_bounds__(THREADS, 8)
void lut_kernel(const float* __restrict__ table,
                const void* __restrict__ mraw,
                float* __restrict__ out) {
    __shared__ __align__(16) float s_m[OT][KTAB];   // Mobius coeffs
    __shared__ int s_off[OT][NIN];
    __shared__ int s_is64;

    const int tid   = threadIdx.x;
    const int obase = blockIdx.x * OT;
    const int bbase = blockIdx.y * BT;

    // Detect mapping dtype: int64 values < 2048 => odd 32-bit words are 0.
    const int* w32 = (const int*)mraw;
    if (tid == 0) {
        int z = 1;
#pragma unroll
        for (int i = 1; i < 16; i += 2) z &= (w32[i] == 0);
        s_is64 = z;
    }
    __syncthreads();
    const int is64 = s_is64;

    if (tid < OT * NIN) {
        int idx = (obase + tid / NIN) * NIN + (tid % NIN);
        int m = is64 ? (int)((const long long*)mraw)[idx] : w32[idx];
        s_off[tid / NIN][tid % NIN] = m * BATCH + bbase;
    }

    // Sigmoid of the table tile (OT*KTAB = 256 entries).
    float* mf = &s_m[0][0];
#pragma unroll
    for (int i = tid; i < OT * KTAB; i += THREADS) {
        float t = table[(size_t)(obase + (i >> 6)) * KTAB + (i & 63)];
        mf[i] = 1.0f / (1.0f + __expf(-t));
    }
    // In-place Mobius transform over the 6 index bits (per output row).
#pragma unroll
    for (int bit = 0; bit < NIN; bit++) {
        __syncthreads();
        int msk = 1 << bit;
#pragma unroll
        for (int i = tid; i < OT * KTAB; i += THREADS) {
            if (i & msk) mf[i] -= mf[i ^ msk];
        }
    }
    __syncthreads();

    const int b0 = BPT * tid;   // 4 contiguous batches

    float res[OT][BPT];

#pragma unroll
    for (int o = 0; o < OT; o++) {
        // Early dims (0-2) + dim3; dims 4,5 loaded just-in-time below.
        ull X0[2], X1[2], X2[2], X3[2];
        {
            ulonglong2 u0 = *(const ulonglong2*)(g_xT + s_off[o][0] + b0);
            ulonglong2 u1 = *(const ulonglong2*)(g_xT + s_off[o][1] + b0);
            ulonglong2 u2 = *(const ulonglong2*)(g_xT + s_off[o][2] + b0);
            ulonglong2 u3 = *(const ulonglong2*)(g_xT + s_off[o][3] + b0);
            X0[0] = u0.x; X0[1] = u0.y;
            X1[0] = u1.x; X1[1] = u1.y;
            X2[0] = u2.x; X2[1] = u2.y;
            X3[0] = u3.x; X3[1] = u3.y;
        }

        const float4* c4 = (const float4*)&s_m[o][0];

        // Depth-first Horner tree: quads (bits 0-1), merges (bits 2-5);
        // every merge is a single fma: y = even + x * odd.
        ull st2[2], st3[2], st4[2], rr[2];
        ull X4[2], X5[2];
#pragma unroll
        for (int t = 0; t < 8; t++) {
            ull w0[2], w1[2], y[2];
            {
                float4 c = c4[2 * t];
                ull C0 = dup2(c.x), C1 = dup2(c.y), C2 = dup2(c.z), C3 = dup2(c.w);
#pragma unroll
                for (int p = 0; p < 2; p++) {
                    ull u = fma2(X0[p], C1, C0);
                    ull v = fma2(X0[p], C3, C2);
                    w0[p] = fma2(X1[p], v, u);
                }
            }
            {
                float4 c = c4[2 * t + 1];
                ull C0 = dup2(c.x), C1 = dup2(c.y), C2 = dup2(c.z), C3 = dup2(c.w);
#pragma unroll
                for (int p = 0; p < 2; p++) {
                    ull u = fma2(X0[p], C1, C0);
                    ull v = fma2(X0[p], C3, C2);
                    w1[p] = fma2(X1[p], v, u);
                }
            }
#pragma unroll
            for (int p = 0; p < 2; p++) y[p] = fma2(X2[p], w1[p], w0[p]);

            if ((t & 1) == 0) {
                st2[0] = y[0]; st2[1] = y[1];
            } else {
#pragma unroll
                for (int p = 0; p < 2; p++) y[p] = fma2(X3[p], y[p], st2[p]);
                if ((t & 2) == 0) {
                    st3[0] = y[0]; st3[1] = y[1];
                } else {
#pragma unroll
                    for (int p = 0; p < 2; p++) y[p] = fma2(X4[p], y[p], st3[p]);
                    if ((t & 4) == 0) {
                        st4[0] = y[0]; st4[1] = y[1];
                    } else {
#pragma unroll
                        for (int p = 0; p < 2; p++)
                            rr[p] = fma2(X5[p], y[p], st4[p]);
                    }
                }
            }

            // Just-in-time loads: dim4 after group 1 (first use t=3),
            // dim5 after group 3 (first use t=7) — short live ranges.
            if (t == 1) {
                ulonglong2 u4 = *(const ulonglong2*)(g_xT + s_off[o][4] + b0);
                X4[0] = u4.x; X4[1] = u4.y;
            }
            if (t == 3) {
                ulonglong2 u5 = *(const ulonglong2*)(g_xT + s_off[o][5] + b0);
                X5[0] = u5.x; X5[1] = u5.y;
            }
        }

        float2 f0 = unpack2(rr[0]), f1 = unpack2(rr[1]);
        res[o][0] = f0.x; res[o][1] = f0.y;
        res[o][2] = f1.x; res[o][3] = f1.y;
    }

    // 16B contiguous per batch row (4 outputs), 4 rows per thread.
#pragma unroll
    for (int j = 0; j < BPT; j++)
        *(float4*)(out + (size_t)(bbase + b0 + j) * OSIZE + obase) =
            make_float4(res[0][j], res[1][j], res[2][j], res[3][j]);
}

// ---------------------------------------------------------------------------
extern "C" void kernel_launch(void* const* d_in, const int* in_sizes, int n_in,
                              void* d_out, int out_size) {
    const float* x     = (const float*)d_in[0];
    const float* table = (const float*)d_in[1];
    const void*  mraw  = d_in[2];
    float*       out   = (float*)d_out;

    (void)in_sizes; (void)n_in; (void)out_size;

    transpose_kernel<<<dim3(ISIZE / 32, BATCH / 32), dim3(32, 8)>>>(x);
    lut_kernel<<<dim3(OSIZE / OT, BATCH / BT), THREADS>>>(table, mraw, out);
}